// round 16
// baseline (speedup 1.0000x reference)
#include <cuda_runtime.h>
#include <cuda_fp16.h>

#define N_NODES 100000
#define E_EDGES 1600000
#define D 64
#define CAP 64

// Scratch
__device__ __half2 g_xh[N_NODES * 32];       // fp16 copy of x (12.8 MB)
__device__ int g_cursor[3][N_NODES];         // bucket fill count == degree
__device__ int g_bucket[3][N_NODES * CAP];   // padded src buckets (76.8 MB)
__device__ __half2 g_meanh[N_NODES * 96];    // per-etype means, fp16 (38.4 MB)
__device__ __half g_wh[3][64][64];           // fp16 copy of W0|W1|W2

// ---------------------------------------------------------------------------
// Prep: x -> half2 copy, W -> fp16, zero cursors.
// ---------------------------------------------------------------------------
__global__ __launch_bounds__(256) void k_prep(
    const float2* __restrict__ x2,
    const float* __restrict__ W0, const float* __restrict__ W1,
    const float* __restrict__ W2)
{
    int idx = blockIdx.x * blockDim.x + threadIdx.x;
    int stride = gridDim.x * blockDim.x;
    const int nh = N_NODES * 32;
    for (int i = idx; i < nh; i += stride) {
        float2 v = x2[i];
        g_xh[i] = __floats2half2_rn(v.x, v.y);
    }
    int* cur = &g_cursor[0][0];
    for (int i = idx; i < 3 * N_NODES; i += stride) cur[i] = 0;
    __half* wh = &g_wh[0][0][0];
    for (int i = idx; i < 3 * 4096; i += stride) {
        int e = i >> 12;
        int r = i & 4095;
        float v = (e == 0) ? W0[r] : (e == 1) ? W1[r] : W2[r];
        wh[i] = __float2half_rn(v);
    }
}

// ---------------------------------------------------------------------------
// Scatter into fixed-capacity buckets: ONE pass, 4 edges/thread/iter.
// ---------------------------------------------------------------------------
__global__ __launch_bounds__(256) void k_scatter(
    const int4* __restrict__ s0, const int4* __restrict__ d0,
    const int4* __restrict__ s1, const int4* __restrict__ d1,
    const int4* __restrict__ s2, const int4* __restrict__ d2)
{
    int e = blockIdx.y;
    const int4* __restrict__ src4 = (e == 0) ? s0 : (e == 1) ? s1 : s2;
    const int4* __restrict__ dst4 = (e == 0) ? d0 : (e == 1) ? d1 : d2;
    int* cursor = g_cursor[e];
    int* bucket = g_bucket[e];
    int idx = blockIdx.x * blockDim.x + threadIdx.x;
    int stride = gridDim.x * blockDim.x;
    const int n4 = E_EDGES / 4;
    for (int i = idx; i < n4; i += stride) {
        int4 d = __ldg(&dst4[i]);
        int4 s = __ldg(&src4[i]);
        int p0 = atomicAdd(cursor + d.x, 1);
        int p1 = atomicAdd(cursor + d.y, 1);
        int p2 = atomicAdd(cursor + d.z, 1);
        int p3 = atomicAdd(cursor + d.w, 1);
        if (p0 < CAP) bucket[d.x * CAP + p0] = s.x;
        if (p1 < CAP) bucket[d.y * CAP + p1] = s.y;
        if (p2 < CAP) bucket[d.z * CAP + p2] = s.z;
        if (p3 < CAP) bucket[d.w * CAP + p3] = s.w;
    }
}

// ---------------------------------------------------------------------------
// Gather + mean: FOUR nodes per warp (8 lanes each), LDG.128 row loads,
// 16-edge chunks (two interleaved 8-unrolls) for deeper MLP. Means fp16.
// ---------------------------------------------------------------------------
__global__ __launch_bounds__(256) void k_mean() {
    int tid  = threadIdx.x;
    int lane = tid & 31;
    int wid  = tid >> 5;
    int sub  = lane >> 3;      // node within warp (0..3)
    int ol   = lane & 7;       // column octet
    int sb   = sub << 3;

    int gw = blockIdx.x * 8 + wid;
    int nwarps = gridDim.x * 8;

    for (int nb = gw * 4; nb < N_NODES; nb += nwarps * 4) {
        int n = nb + sub;
        #pragma unroll
        for (int e = 0; e < 3; e++) {
            int cnt = min(g_cursor[e][n], CAP);
            const int* __restrict__ bkp = g_bucket[e] + n * CAP;

            int cmax = cnt;
            cmax = max(cmax, __shfl_xor_sync(0xffffffffu, cmax, 8));
            cmax = max(cmax, __shfl_xor_sync(0xffffffffu, cmax, 16));

            float a0 = 0.f, a1 = 0.f, a2 = 0.f, a3 = 0.f;
            float a4 = 0.f, a5 = 0.f, a6 = 0.f, a7 = 0.f;

            for (int base = 0; base < cmax; base += 16) {
                int i0 = base + ol;
                int i1 = base + 8 + ol;
                int id0 = (i0 < cnt) ? __ldg(bkp + i0) : 0;
                int id1 = (i1 < cnt) ? __ldg(bkp + i1) : 0;
                #pragma unroll
                for (int j = 0; j < 8; j++) {
                    int s = __shfl_sync(0xffffffffu, id0, sb + j);
                    if (base + j < cnt) {
                        uint4 v = *reinterpret_cast<const uint4*>(
                            g_xh + s * 32 + ol * 4);
                        float2 f0 = __half22float2(*reinterpret_cast<__half2*>(&v.x));
                        float2 f1 = __half22float2(*reinterpret_cast<__half2*>(&v.y));
                        float2 f2 = __half22float2(*reinterpret_cast<__half2*>(&v.z));
                        float2 f3 = __half22float2(*reinterpret_cast<__half2*>(&v.w));
                        a0 += f0.x; a1 += f0.y; a2 += f1.x; a3 += f1.y;
                        a4 += f2.x; a5 += f2.y; a6 += f3.x; a7 += f3.y;
                    }
                }
                #pragma unroll
                for (int j = 0; j < 8; j++) {
                    int s = __shfl_sync(0xffffffffu, id1, sb + j);
                    if (base + 8 + j < cnt) {
                        uint4 v = *reinterpret_cast<const uint4*>(
                            g_xh + s * 32 + ol * 4);
                        float2 f0 = __half22float2(*reinterpret_cast<__half2*>(&v.x));
                        float2 f1 = __half22float2(*reinterpret_cast<__half2*>(&v.y));
                        float2 f2 = __half22float2(*reinterpret_cast<__half2*>(&v.z));
                        float2 f3 = __half22float2(*reinterpret_cast<__half2*>(&v.w));
                        a0 += f0.x; a1 += f0.y; a2 += f1.x; a3 += f1.y;
                        a4 += f2.x; a5 += f2.y; a6 += f3.x; a7 += f3.y;
                    }
                }
            }

            float inv = (cnt > 0) ? (1.0f / (float)cnt) : 0.f;
            uint4 o;
            __half2 h0 = __floats2half2_rn(a0 * inv, a1 * inv);
            __half2 h1 = __floats2half2_rn(a2 * inv, a3 * inv);
            __half2 h2 = __floats2half2_rn(a4 * inv, a5 * inv);
            __half2 h3 = __floats2half2_rn(a6 * inv, a7 * inv);
            o.x = *reinterpret_cast<unsigned*>(&h0);
            o.y = *reinterpret_cast<unsigned*>(&h1);
            o.z = *reinterpret_cast<unsigned*>(&h2);
            o.w = *reinterpret_cast<unsigned*>(&h3);
            *reinterpret_cast<uint4*>(g_meanh + (size_t)n * 96 + e * 32 + ol * 4) = o;
        }
    }
}

// ---------------------------------------------------------------------------
// HMMA GEMM: 160-node tile (625 blocks), 256 threads / 8 warps.
// Warp = (mg = warp>>2 : 5 m16-tiles, ng = warp&3 : 16 cols). Each A
// ldmatrix.x4 feeds TWO n8 mma -> half the LDS per node vs n8-per-warp.
// ---------------------------------------------------------------------------
#define ASTR 200

__global__ __launch_bounds__(256, 2) void k_gemm(
    const float* __restrict__ b0, const float* __restrict__ b1,
    const float* __restrict__ b2, float* __restrict__ out)
{
    extern __shared__ __align__(16) __half smh[];
    __half* Ash = smh;                                      // 160*200 halves
    float* msk = reinterpret_cast<float*>(smh + 160 * ASTR);  // 3*160

    int tid = threadIdx.x;
    int tile0 = blockIdx.x * 160;

    // stage A tile: 160 rows x 24 uint4
    {
        const uint4* mrows = reinterpret_cast<const uint4*>(g_meanh) +
                             (size_t)tile0 * 24;
        for (int i = tid; i < 160 * 24; i += 256) {
            int row = i / 24;
            int ch  = i % 24;
            uint4 v = __ldg(&mrows[(size_t)row * 24 + ch]);
            *reinterpret_cast<uint4*>(Ash + row * ASTR + ch * 8) = v;
        }
    }
    for (int i = tid; i < 480; i += 256) {
        int e = i / 160;
        int r = i % 160;
        msk[i] = (g_cursor[e][tile0 + r] > 0) ? 1.f : 0.f;
    }
    __syncthreads();

    int warp = tid >> 5;
    int lane = tid & 31;
    int ng   = warp & 3;       // n-group: cols 16*ng .. 16*ng+15
    int mg   = warp >> 2;      // m-group: m16 tiles mg*5 .. mg*5+4
    int n0   = ng * 16;
    int tig  = lane & 3;
    int gid  = lane >> 2;

    // B fragments: 12 k-steps x 2 n8-strips x 2 regs
    unsigned Bf[12][2][2];
    #pragma unroll
    for (int ks = 0; ks < 12; ks++) {
        int e  = ks >> 2;
        int kl = (ks & 3) * 16;
        #pragma unroll
        for (int st = 0; st < 2; st++) {
            int nn = n0 + st * 8 + gid;
            __half w00 = g_wh[e][kl + tig * 2 + 0][nn];
            __half w01 = g_wh[e][kl + tig * 2 + 1][nn];
            __half w10 = g_wh[e][kl + 8 + tig * 2 + 0][nn];
            __half w11 = g_wh[e][kl + 8 + tig * 2 + 1][nn];
            __half2 p0 = __halves2half2(w00, w01);
            __half2 p1 = __halves2half2(w10, w11);
            Bf[ks][st][0] = *reinterpret_cast<unsigned*>(&p0);
            Bf[ks][st][1] = *reinterpret_cast<unsigned*>(&p1);
        }
    }

    unsigned ash_u32 = (unsigned)__cvta_generic_to_shared(Ash);
    int lr = (lane & 7) + ((lane >> 3) & 1) * 8;   // row offset within m16
    int lc = ((lane >> 4) & 1) * 8;                // col offset within k16

    float acc[5][2][4];
    #pragma unroll
    for (int m = 0; m < 5; m++)
        #pragma unroll
        for (int st = 0; st < 2; st++)
            #pragma unroll
            for (int j = 0; j < 4; j++) acc[m][st][j] = 0.f;

    #pragma unroll
    for (int ks = 0; ks < 12; ks++) {
        int kglob = ks * 16;
        #pragma unroll
        for (int m = 0; m < 5; m++) {
            int mt = mg * 5 + m;
            unsigned addr = ash_u32 +
                ((unsigned)((mt * 16 + lr) * ASTR + kglob + lc) << 1);
            unsigned a0, a1, a2, a3;
            asm volatile(
                "ldmatrix.sync.aligned.m8n8.x4.shared.b16 {%0,%1,%2,%3}, [%4];"
                : "=r"(a0), "=r"(a1), "=r"(a2), "=r"(a3) : "r"(addr));
            #pragma unroll
            for (int st = 0; st < 2; st++) {
                asm volatile(
                    "mma.sync.aligned.m16n8k16.row.col.f32.f16.f16.f32 "
                    "{%0,%1,%2,%3}, {%4,%5,%6,%7}, {%8,%9}, {%0,%1,%2,%3};"
                    : "+f"(acc[m][st][0]), "+f"(acc[m][st][1]),
                      "+f"(acc[m][st][2]), "+f"(acc[m][st][3])
                    : "r"(a0), "r"(a1), "r"(a2), "r"(a3),
                      "r"(Bf[ks][st][0]), "r"(Bf[ks][st][1]));
            }
        }
    }

    // epilogue: masked bias + writeback (per strip)
    #pragma unroll
    for (int st = 0; st < 2; st++) {
        int col = n0 + st * 8 + tig * 2;
        float be0[3], be1[3];
        be0[0] = __ldg(&b0[col]); be1[0] = __ldg(&b0[col + 1]);
        be0[1] = __ldg(&b1[col]); be1[1] = __ldg(&b1[col + 1]);
        be0[2] = __ldg(&b2[col]); be1[2] = __ldg(&b2[col + 1]);

        #pragma unroll
        for (int m = 0; m < 5; m++) {
            int mt = mg * 5 + m;
            int row0 = mt * 16 + gid;
            int row1 = row0 + 8;
            float r0 = acc[m][st][0], r1 = acc[m][st][1];
            float r2 = acc[m][st][2], r3 = acc[m][st][3];
            #pragma unroll
            for (int e = 0; e < 3; e++) {
                float mk0 = msk[e * 160 + row0];
                float mk1 = msk[e * 160 + row1];
                r0 += mk0 * be0[e]; r1 += mk0 * be1[e];
                r2 += mk1 * be0[e]; r3 += mk1 * be1[e];
            }
            *reinterpret_cast<float2*>(out + (size_t)(tile0 + row0) * 64 + col) =
                make_float2(r0, r1);
            *reinterpret_cast<float2*>(out + (size_t)(tile0 + row1) * 64 + col) =
                make_float2(r2, r3);
        }
    }
}

// ---------------------------------------------------------------------------
extern "C" void kernel_launch(void* const* d_in, const int* in_sizes, int n_in,
                              void* d_out, int out_size)
{
    const float* x  = (const float*)d_in[0];
    const float* W0 = (const float*)d_in[1];
    const float* b0 = (const float*)d_in[2];
    const int*   s0 = (const int*)  d_in[3];
    const int*   t0 = (const int*)  d_in[4];
    const float* W1 = (const float*)d_in[5];
    const float* b1 = (const float*)d_in[6];
    const int*   s1 = (const int*)  d_in[7];
    const int*   t1 = (const int*)  d_in[8];
    const float* W2 = (const float*)d_in[9];
    const float* b2 = (const float*)d_in[10];
    const int*   s2 = (const int*)  d_in[11];
    const int*   t2 = (const int*)  d_in[12];
    float* out = (float*)d_out;

    k_prep<<<1024, 256>>>(reinterpret_cast<const float2*>(x), W0, W1, W2);

    dim3 gS(1563, 3);
    k_scatter<<<gS, 256>>>((const int4*)s0, (const int4*)t0,
                           (const int4*)s1, (const int4*)t1,
                           (const int4*)s2, (const int4*)t2);

    k_mean<<<1184, 256>>>();

    int smem = 160 * ASTR * 2 + 3 * 160 * 4;   // A tile + masks
    cudaFuncSetAttribute(k_gemm,
                         cudaFuncAttributeMaxDynamicSharedMemorySize, smem);
    k_gemm<<<N_NODES / 160, 256, smem>>>(b0, b1, b2, out);
}

// round 17
// speedup vs baseline: 1.0391x; 1.0391x over previous
#include <cuda_runtime.h>
#include <cuda_fp16.h>

#define N_NODES 100000
#define E_EDGES 1600000
#define D 64
#define CAP 64

// Scratch
__device__ __half2 g_xh[N_NODES * 32];       // fp16 copy of x (12.8 MB)
__device__ int g_cursor[3][N_NODES];         // bucket fill count == degree
__device__ int g_bucket[3][N_NODES * CAP];   // padded src buckets (76.8 MB)
__device__ __half2 g_meanh[N_NODES * 96];    // per-etype means, fp16 (38.4 MB)
__device__ __half g_whT[3][64][64];          // W^T fp16: [e][n][k]

// ---------------------------------------------------------------------------
// Prep: x -> half2 copy, W -> fp16 transposed, zero cursors.
// ---------------------------------------------------------------------------
__global__ __launch_bounds__(256) void k_prep(
    const float2* __restrict__ x2,
    const float* __restrict__ W0, const float* __restrict__ W1,
    const float* __restrict__ W2)
{
    int idx = blockIdx.x * blockDim.x + threadIdx.x;
    int stride = gridDim.x * blockDim.x;
    const int nh = N_NODES * 32;
    for (int i = idx; i < nh; i += stride) {
        float2 v = x2[i];
        g_xh[i] = __floats2half2_rn(v.x, v.y);
    }
    int* cur = &g_cursor[0][0];
    for (int i = idx; i < 3 * N_NODES; i += stride) cur[i] = 0;
    __half* whT = &g_whT[0][0][0];
    for (int i = idx; i < 3 * 4096; i += stride) {
        int e = i >> 12;
        int r = i & 4095;
        int n = r >> 6;
        int k = r & 63;
        const float* W = (e == 0) ? W0 : (e == 1) ? W1 : W2;
        whT[i] = __float2half_rn(W[k * 64 + n]);
    }
}

// ---------------------------------------------------------------------------
// Scatter into fixed-capacity buckets: ONE pass, 4 edges/thread/iter.
// ---------------------------------------------------------------------------
__global__ __launch_bounds__(256) void k_scatter(
    const int4* __restrict__ s0, const int4* __restrict__ d0,
    const int4* __restrict__ s1, const int4* __restrict__ d1,
    const int4* __restrict__ s2, const int4* __restrict__ d2)
{
    int e = blockIdx.y;
    const int4* __restrict__ src4 = (e == 0) ? s0 : (e == 1) ? s1 : s2;
    const int4* __restrict__ dst4 = (e == 0) ? d0 : (e == 1) ? d1 : d2;
    int* cursor = g_cursor[e];
    int* bucket = g_bucket[e];
    int idx = blockIdx.x * blockDim.x + threadIdx.x;
    int stride = gridDim.x * blockDim.x;
    const int n4 = E_EDGES / 4;
    for (int i = idx; i < n4; i += stride) {
        int4 d = __ldg(&dst4[i]);
        int4 s = __ldg(&src4[i]);
        int p0 = atomicAdd(cursor + d.x, 1);
        int p1 = atomicAdd(cursor + d.y, 1);
        int p2 = atomicAdd(cursor + d.z, 1);
        int p3 = atomicAdd(cursor + d.w, 1);
        if (p0 < CAP) bucket[d.x * CAP + p0] = s.x;
        if (p1 < CAP) bucket[d.y * CAP + p1] = s.y;
        if (p2 < CAP) bucket[d.z * CAP + p2] = s.z;
        if (p3 < CAP) bucket[d.w * CAP + p3] = s.w;
    }
}

// ---------------------------------------------------------------------------
// Gather + mean: FOUR nodes per warp (8 lanes each), LDG.128 row loads,
// 8-edge unrolled chunks (proven R15 form). Means written fp16.
// ---------------------------------------------------------------------------
__global__ __launch_bounds__(256) void k_mean() {
    int tid  = threadIdx.x;
    int lane = tid & 31;
    int wid  = tid >> 5;
    int sub  = lane >> 3;      // node within warp (0..3)
    int ol   = lane & 7;       // column octet
    int sb   = sub << 3;

    int gw = blockIdx.x * 8 + wid;
    int nwarps = gridDim.x * 8;

    for (int nb = gw * 4; nb < N_NODES; nb += nwarps * 4) {
        int n = nb + sub;
        #pragma unroll
        for (int e = 0; e < 3; e++) {
            int cnt = min(g_cursor[e][n], CAP);
            const int* __restrict__ bkp = g_bucket[e] + n * CAP;

            int cmax = cnt;
            cmax = max(cmax, __shfl_xor_sync(0xffffffffu, cmax, 8));
            cmax = max(cmax, __shfl_xor_sync(0xffffffffu, cmax, 16));

            float a0 = 0.f, a1 = 0.f, a2 = 0.f, a3 = 0.f;
            float a4 = 0.f, a5 = 0.f, a6 = 0.f, a7 = 0.f;

            for (int base = 0; base < cmax; base += 8) {
                int myi = base + ol;
                int id = (myi < cnt) ? __ldg(bkp + myi) : 0;
                #pragma unroll
                for (int j = 0; j < 8; j++) {
                    int s = __shfl_sync(0xffffffffu, id, sb + j);
                    if (base + j < cnt) {
                        uint4 v = *reinterpret_cast<const uint4*>(
                            g_xh + s * 32 + ol * 4);
                        float2 f0 = __half22float2(*reinterpret_cast<__half2*>(&v.x));
                        float2 f1 = __half22float2(*reinterpret_cast<__half2*>(&v.y));
                        float2 f2 = __half22float2(*reinterpret_cast<__half2*>(&v.z));
                        float2 f3 = __half22float2(*reinterpret_cast<__half2*>(&v.w));
                        a0 += f0.x; a1 += f0.y; a2 += f1.x; a3 += f1.y;
                        a4 += f2.x; a5 += f2.y; a6 += f3.x; a7 += f3.y;
                    }
                }
            }

            float inv = (cnt > 0) ? (1.0f / (float)cnt) : 0.f;
            uint4 o;
            __half2 h0 = __floats2half2_rn(a0 * inv, a1 * inv);
            __half2 h1 = __floats2half2_rn(a2 * inv, a3 * inv);
            __half2 h2 = __floats2half2_rn(a4 * inv, a5 * inv);
            __half2 h3 = __floats2half2_rn(a6 * inv, a7 * inv);
            o.x = *reinterpret_cast<unsigned*>(&h0);
            o.y = *reinterpret_cast<unsigned*>(&h1);
            o.z = *reinterpret_cast<unsigned*>(&h2);
            o.w = *reinterpret_cast<unsigned*>(&h3);
            *reinterpret_cast<uint4*>(g_meanh + (size_t)n * 96 + e * 32 + ol * 4) = o;
        }
    }
}

// ---------------------------------------------------------------------------
// HMMA GEMM: 96-row tile (1042 blocks, last partial), 256 threads / 8 warps.
// Warp = (mg = warp>>2 : 3 m16-tiles, ng = warp&3 : 16 cols). Each A
// ldmatrix.x4 feeds TWO n8 mma; B frags loaded per k-step from g_whT (L1).
// ---------------------------------------------------------------------------
#define TROWS 96
#define ASTR 200

__global__ __launch_bounds__(256) void k_gemm(
    const float* __restrict__ b0, const float* __restrict__ b1,
    const float* __restrict__ b2, float* __restrict__ out)
{
    extern __shared__ __align__(16) __half smh[];
    __half* Ash = smh;                                        // 96*200 halves
    float* msk = reinterpret_cast<float*>(smh + TROWS * ASTR);  // 3*96

    int tid = threadIdx.x;
    int tile0 = blockIdx.x * TROWS;

    // stage A tile: 96 rows x 24 uint4 (guard tail rows -> zero)
    {
        const uint4* mrows = reinterpret_cast<const uint4*>(g_meanh);
        for (int i = tid; i < TROWS * 24; i += 256) {
            int row = i / 24;
            int ch  = i % 24;
            int grow = tile0 + row;
            uint4 v = make_uint4(0u, 0u, 0u, 0u);
            if (grow < N_NODES) v = __ldg(&mrows[(size_t)grow * 24 + ch]);
            *reinterpret_cast<uint4*>(Ash + row * ASTR + ch * 8) = v;
        }
    }
    for (int i = tid; i < 3 * TROWS; i += 256) {
        int e = i / TROWS;
        int r = i % TROWS;
        int grow = tile0 + r;
        msk[i] = (grow < N_NODES && g_cursor[e][grow] > 0) ? 1.f : 0.f;
    }
    __syncthreads();

    int warp = tid >> 5;
    int lane = tid & 31;
    int ng   = warp & 3;       // n-group: cols 16*ng .. 16*ng+15
    int mg   = warp >> 2;      // m-group: m16 tiles mg*3 .. mg*3+2
    int n0   = ng * 16;
    int tig  = lane & 3;
    int gid  = lane >> 2;

    unsigned ash_u32 = (unsigned)__cvta_generic_to_shared(Ash);
    int lr = (lane & 7) + ((lane >> 3) & 1) * 8;   // row offset within m16
    int lc = ((lane >> 4) & 1) * 8;                // col offset within k16

    float acc[3][2][4];
    #pragma unroll
    for (int m = 0; m < 3; m++)
        #pragma unroll
        for (int st = 0; st < 2; st++)
            #pragma unroll
            for (int j = 0; j < 4; j++) acc[m][st][j] = 0.f;

    #pragma unroll
    for (int ks = 0; ks < 12; ks++) {
        int e  = ks >> 2;
        int kl = (ks & 3) * 16;

        // B fragments for this k-step: contiguous 4B loads from W^T (L1-hot)
        unsigned Bf[2][2];
        #pragma unroll
        for (int st = 0; st < 2; st++) {
            int nn = n0 + st * 8 + gid;
            __half2 p0 = *reinterpret_cast<const __half2*>(
                &g_whT[e][nn][kl + tig * 2]);
            __half2 p1 = *reinterpret_cast<const __half2*>(
                &g_whT[e][nn][kl + 8 + tig * 2]);
            Bf[st][0] = *reinterpret_cast<unsigned*>(&p0);
            Bf[st][1] = *reinterpret_cast<unsigned*>(&p1);
        }

        int kglob = ks * 16;
        #pragma unroll
        for (int m = 0; m < 3; m++) {
            int mt = mg * 3 + m;
            unsigned addr = ash_u32 +
                ((unsigned)((mt * 16 + lr) * ASTR + kglob + lc) << 1);
            unsigned a0, a1, a2, a3;
            asm volatile(
                "ldmatrix.sync.aligned.m8n8.x4.shared.b16 {%0,%1,%2,%3}, [%4];"
                : "=r"(a0), "=r"(a1), "=r"(a2), "=r"(a3) : "r"(addr));
            #pragma unroll
            for (int st = 0; st < 2; st++) {
                asm volatile(
                    "mma.sync.aligned.m16n8k16.row.col.f32.f16.f16.f32 "
                    "{%0,%1,%2,%3}, {%4,%5,%6,%7}, {%8,%9}, {%0,%1,%2,%3};"
                    : "+f"(acc[m][st][0]), "+f"(acc[m][st][1]),
                      "+f"(acc[m][st][2]), "+f"(acc[m][st][3])
                    : "r"(a0), "r"(a1), "r"(a2), "r"(a3),
                      "r"(Bf[st][0]), "r"(Bf[st][1]));
            }
        }
    }

    // epilogue: masked bias + writeback (guard tail rows)
    #pragma unroll
    for (int st = 0; st < 2; st++) {
        int col = n0 + st * 8 + tig * 2;
        float be0[3], be1[3];
        be0[0] = __ldg(&b0[col]); be1[0] = __ldg(&b0[col + 1]);
        be0[1] = __ldg(&b1[col]); be1[1] = __ldg(&b1[col + 1]);
        be0[2] = __ldg(&b2[col]); be1[2] = __ldg(&b2[col + 1]);

        #pragma unroll
        for (int m = 0; m < 3; m++) {
            int mt = mg * 3 + m;
            int row0 = mt * 16 + gid;
            int row1 = row0 + 8;
            float r0 = acc[m][st][0], r1 = acc[m][st][1];
            float r2 = acc[m][st][2], r3 = acc[m][st][3];
            #pragma unroll
            for (int e = 0; e < 3; e++) {
                float mk0 = msk[e * TROWS + row0];
                float mk1 = msk[e * TROWS + row1];
                r0 += mk0 * be0[e]; r1 += mk0 * be1[e];
                r2 += mk1 * be0[e]; r3 += mk1 * be1[e];
            }
            if (tile0 + row0 < N_NODES)
                *reinterpret_cast<float2*>(
                    out + (size_t)(tile0 + row0) * 64 + col) = make_float2(r0, r1);
            if (tile0 + row1 < N_NODES)
                *reinterpret_cast<float2*>(
                    out + (size_t)(tile0 + row1) * 64 + col) = make_float2(r2, r3);
        }
    }
}

// ---------------------------------------------------------------------------
extern "C" void kernel_launch(void* const* d_in, const int* in_sizes, int n_in,
                              void* d_out, int out_size)
{
    const float* x  = (const float*)d_in[0];
    const float* W0 = (const float*)d_in[1];
    const float* b0 = (const float*)d_in[2];
    const int*   s0 = (const int*)  d_in[3];
    const int*   t0 = (const int*)  d_in[4];
    const float* W1 = (const float*)d_in[5];
    const float* b1 = (const float*)d_in[6];
    const int*   s1 = (const int*)  d_in[7];
    const int*   t1 = (const int*)  d_in[8];
    const float* W2 = (const float*)d_in[9];
    const float* b2 = (const float*)d_in[10];
    const int*   s2 = (const int*)  d_in[11];
    const int*   t2 = (const int*)  d_in[12];
    float* out = (float*)d_out;

    k_prep<<<1024, 256>>>(reinterpret_cast<const float2*>(x), W0, W1, W2);

    dim3 gS(1563, 3);
    k_scatter<<<gS, 256>>>((const int4*)s0, (const int4*)t0,
                           (const int4*)s1, (const int4*)t1,
                           (const int4*)s2, (const int4*)t2);

    k_mean<<<1184, 256>>>();

    int smem = TROWS * ASTR * 2 + 3 * TROWS * 4;   // A tile + masks
    cudaFuncSetAttribute(k_gemm,
                         cudaFuncAttributeMaxDynamicSharedMemorySize, smem);
    k_gemm<<<(N_NODES + TROWS - 1) / TROWS, 256, smem>>>(b0, b1, b2, out);
}